// round 15
// baseline (speedup 1.0000x reference)
#include <cuda_runtime.h>
#include <cuda_bf16.h>
#include <cstdint>

typedef unsigned long long ull;

// ---------------- problem constants ----------------
#define Bsz   64
#define Tn    256
#define Lc    20
#define WD    300
#define CDm   100
#define PDm   100
#define NF    100
#define CVv   100
#define Hh    256
#define D0r   500
#define DP    512
#define G4    1024
#define NW    2048
#define BT    (Bsz*Tn)
#define OUTW  (2*Hh)

// ---------------- scratch (device globals; no runtime alloc) ----------------
__device__ __align__(256) float d_x0[BT*DP];
__device__ __align__(256) float d_x1[BT*OUTW];
__device__ __align__(256) float d_x2[BT*OUTW];
__device__ __align__(256) float d_gx[(size_t)BT*NW];
__device__ __align__(256) float d_wpad[NW*DP];
__device__ float d_U[CVv*3*NF];
__device__ __align__(256) unsigned short d_hh[2][2][Hh*Bsz];  // h hi bf16 [parity][dir][j*64+b]
__device__ __align__(256) unsigned short d_hl[2][2][Hh*Bsz];  // h lo bf16
__device__ __align__(256) __nv_bfloat16 d_Ah[BT*DP];
__device__ __align__(256) __nv_bfloat16 d_Al[BT*DP];
__device__ __align__(256) __nv_bfloat16 d_Wh0[NW*DP];
__device__ __align__(256) __nv_bfloat16 d_Wl0[NW*DP];
__device__ __align__(256) __nv_bfloat16 d_Wh1[NW*DP];
__device__ __align__(256) __nv_bfloat16 d_Wl1[NW*DP];
__device__ __align__(256) __nv_bfloat16 d_Wh2[NW*DP];
__device__ __align__(256) __nv_bfloat16 d_Wl2[NW*DP];
__device__ __align__(256) unsigned g_cnt2[64];   // [0]=dir0, [32]=dir1 (separate lines)

// ---------------- ptx helpers (compute_103-safe only) ----------------
__device__ __forceinline__ uint32_t s2u(const void* p){
    uint32_t a;
    asm("{ .reg .u64 t; cvta.to.shared.u64 t, %1; cvt.u32.u64 %0, t; }" : "=r"(a) : "l"(p));
    return a;
}
__device__ __forceinline__ void ldsm4(uint32_t* r, uint32_t addr){
    asm volatile("ldmatrix.sync.aligned.m8n8.x4.shared.b16 {%0,%1,%2,%3}, [%4];"
        : "=r"(r[0]), "=r"(r[1]), "=r"(r[2]), "=r"(r[3]) : "r"(addr));
}
__device__ __forceinline__ void ldsm4t(uint32_t* r, uint32_t addr){
    asm volatile("ldmatrix.sync.aligned.m8n8.x4.trans.shared.b16 {%0,%1,%2,%3}, [%4];"
        : "=r"(r[0]), "=r"(r[1]), "=r"(r[2]), "=r"(r[3]) : "r"(addr));
}
__device__ __forceinline__ void mma16816(float* c, const uint32_t* a, const uint32_t* b){
    asm volatile("mma.sync.aligned.m16n8k16.row.col.f32.bf16.bf16.f32 "
        "{%0,%1,%2,%3}, {%4,%5,%6,%7}, {%8,%9}, {%0,%1,%2,%3};"
        : "+f"(c[0]), "+f"(c[1]), "+f"(c[2]), "+f"(c[3])
        : "r"(a[0]), "r"(a[1]), "r"(a[2]), "r"(a[3]), "r"(b[0]), "r"(b[1]));
}
__device__ __forceinline__ void cpa16(uint32_t dst, const void* src){
    asm volatile("cp.async.cg.shared.global [%0], [%1], 16;" :: "r"(dst), "l"(src) : "memory");
}
#define CP_COMMIT() asm volatile("cp.async.commit_group;" ::: "memory")
#define CP_WAIT0()  asm volatile("cp.async.wait_group 0;" ::: "memory")
#define CP_WAIT1()  asm volatile("cp.async.wait_group 1;" ::: "memory")

__device__ __forceinline__ unsigned ld_acq(const unsigned* p){
    unsigned v;
    asm volatile("ld.acquire.gpu.global.b32 %0, [%1];" : "=r"(v) : "l"(p) : "memory");
    return v;
}
__device__ __forceinline__ void red_add_rel(unsigned* p){
    asm volatile("red.release.gpu.global.add.u32 [%0], 1;" :: "l"(p) : "memory");
}

// fast NaN-safe activations (err ~2^-21, budget 1e-3)
__device__ __forceinline__ float fsigmoid(float x){
    return __fdividef(1.f, 1.f + __expf(-x));
}
__device__ __forceinline__ float ftanh(float x){
    return 1.f - __fdividef(2.f, __expf(2.f*x) + 1.f);
}

__device__ __forceinline__ unsigned short bh16(float x){
    __nv_bfloat16 h = __float2bfloat16(x);
    return *(unsigned short*)&h;
}
__device__ __forceinline__ float bh2f(unsigned short u){
    __nv_bfloat16 h = *(__nv_bfloat16*)&u;
    return __bfloat162float(h);
}

// ---------------- fp32 -> bf16 hi/lo split ----------------
__global__ void split_kernel(const float* __restrict__ x,
                             __nv_bfloat16* __restrict__ hi,
                             __nv_bfloat16* __restrict__ lo, int n4)
{
    int i = blockIdx.x*256 + threadIdx.x;
    if (i >= n4) return;
    float4 v = ((const float4*)x)[i];
    float a[4] = {v.x, v.y, v.z, v.w};
    unsigned short hs[4], ls[4];
    #pragma unroll
    for (int j = 0; j < 4; j++) {
        hs[j] = bh16(a[j]);
        ls[j] = bh16(a[j] - bh2f(hs[j]));
    }
    ull hv = (ull)hs[0] | ((ull)hs[1]<<16) | ((ull)hs[2]<<32) | ((ull)hs[3]<<48);
    ull lv = (ull)ls[0] | ((ull)ls[1]<<16) | ((ull)ls[2]<<32) | ((ull)ls[3]<<48);
    *(ull*)(hi + 4*(size_t)i) = hv;
    *(ull*)(lo + 4*(size_t)i) = lv;
}

// ---------------- split-bf16 tensor-core GEMM (unchanged from R8) ----------------
#define SMEM_GB 131072

__global__ void __launch_bounds__(256) gemm_bf16_kernel(
    const __nv_bfloat16* __restrict__ Ah, const __nv_bfloat16* __restrict__ Al,
    const __nv_bfloat16* __restrict__ Wh, const __nv_bfloat16* __restrict__ Wl,
    const float* __restrict__ bias, float* __restrict__ C)
{
    extern __shared__ __align__(1024) char smem[];
    uint32_t sb = s2u(smem);
    int tid = threadIdx.x, lane = tid & 31, wid = tid >> 5;
    int bm = blockIdx.y*128, bn = blockIdx.x*128;
    int wm = (wid >> 1)*32, wn = (wid & 1)*64;

    const __nv_bfloat16* srcs[4];
    srcs[0] = Ah + (size_t)bm*DP;
    srcs[1] = Al + (size_t)bm*DP;
    srcs[2] = Wh + (size_t)bn*DP;
    srcs[3] = Wl + (size_t)bn*DP;

    int r  = tid >> 1;
    int s0 = (tid & 1)*4;
    uint32_t dbase = r*128;

    float acc[2][8][4];
    #pragma unroll
    for (int i = 0; i < 2; i++)
        #pragma unroll
        for (int j = 0; j < 8; j++)
            #pragma unroll
            for (int q = 0; q < 4; q++) acc[i][j][q] = 0.f;

    #pragma unroll
    for (int m = 0; m < 4; m++) {
        const __nv_bfloat16* src = srcs[m] + (size_t)r*DP + s0*8;
        uint32_t d = sb + m*16384 + dbase;
        #pragma unroll
        for (int i = 0; i < 4; i++)
            cpa16(d + (((s0+i)*16) ^ ((r&7)<<4)), src + i*8);
    }
    CP_COMMIT();

    int arow_l = (lane&7) + ((lane&8) ? 8 : 0);
    int akel_l = (lane&16) ? 8 : 0;
    int nrow_l = (lane&7) + ((lane&16) ? 8 : 0);
    int bkel_l = (lane&8) ? 8 : 0;

    for (int ch = 0; ch < 8; ch++) {
        CP_WAIT0();
        __syncthreads();
        if (ch < 7) {
            uint32_t base = sb + ((ch+1)&1)*65536;
            #pragma unroll
            for (int m = 0; m < 4; m++) {
                const __nv_bfloat16* src = srcs[m] + (size_t)r*DP + (ch+1)*64 + s0*8;
                uint32_t d = base + m*16384 + dbase;
                #pragma unroll
                for (int i = 0; i < 4; i++)
                    cpa16(d + (((s0+i)*16) ^ ((r&7)<<4)), src + i*8);
            }
            CP_COMMIT();
        }
        uint32_t bb = sb + (ch&1)*65536;
        #pragma unroll
        for (int s = 0; s < 4; s++) {
            uint32_t a_h[2][4], a_l[2][4];
            #pragma unroll
            for (int mt = 0; mt < 2; mt++) {
                int row = wm + mt*16 + arow_l;
                int kel = s*16 + akel_l;
                uint32_t ad = bb + row*128 + ((kel*2) ^ ((row&7)<<4));
                ldsm4(a_h[mt], ad);
                ldsm4(a_l[mt], ad + 16384);
            }
            uint32_t b_h[8][2], b_l[8][2];
            #pragma unroll
            for (int g = 0; g < 4; g++) {
                int row = wn + g*16 + nrow_l;
                int kel = s*16 + bkel_l;
                uint32_t ad = bb + 32768 + row*128 + ((kel*2) ^ ((row&7)<<4));
                uint32_t t4[4];
                ldsm4(t4, ad);
                b_h[2*g][0] = t4[0]; b_h[2*g][1] = t4[1];
                b_h[2*g+1][0] = t4[2]; b_h[2*g+1][1] = t4[3];
                ldsm4(t4, ad + 16384);
                b_l[2*g][0] = t4[0]; b_l[2*g][1] = t4[1];
                b_l[2*g+1][0] = t4[2]; b_l[2*g+1][1] = t4[3];
            }
            #pragma unroll
            for (int i = 0; i < 2; i++)
                #pragma unroll
                for (int j = 0; j < 8; j++) {
                    mma16816(acc[i][j], a_h[i], b_h[j]);
                    mma16816(acc[i][j], a_h[i], b_l[j]);
                    mma16816(acc[i][j], a_l[i], b_h[j]);
                }
        }
    }

    int rr = lane >> 2, cc = (lane & 3)*2;
    #pragma unroll
    for (int i = 0; i < 2; i++) {
        #pragma unroll
        for (int j = 0; j < 8; j++) {
            int row = bm + wm + i*16 + rr;
            int col = bn + wn + j*8 + cc;
            float bx = __ldg(bias + col), by = __ldg(bias + col + 1);
            float2 v0 = make_float2(acc[i][j][0] + bx, acc[i][j][1] + by);
            float2 v1 = make_float2(acc[i][j][2] + bx, acc[i][j][3] + by);
            *(float2*)(C + (size_t)row*NW + col) = v0;
            *(float2*)(C + (size_t)(row+8)*NW + col) = v1;
        }
    }
}

// ---------------- U[v][k][f] ----------------
__global__ void u_kernel(const float* __restrict__ Ec, const float* __restrict__ cw)
{
    int v = blockIdx.x;
    int f = threadIdx.x;
    __shared__ float e[CDm];
    if (f < CDm) e[f] = Ec[v*CDm + f];
    __syncthreads();
    if (f < NF) {
        float a0 = 0.f, a1 = 0.f, a2 = 0.f;
        #pragma unroll 4
        for (int c = 0; c < CDm; c++) {
            float ev = e[c];
            const float* wp = cw + f*(CDm*3) + c*3;
            a0 += ev*wp[0]; a1 += ev*wp[1]; a2 += ev*wp[2];
        }
        d_U[v*300 +       f] = a0;
        d_U[v*300 + 100 + f] = a1;
        d_U[v*300 + 200 + f] = a2;
    }
}

__global__ void padw_kernel(const float* __restrict__ w0)
{
    int idx = blockIdx.x*256 + threadIdx.x;
    if (idx >= NW*DP) return;
    int n = idx >> 9, k = idx & 511;
    d_wpad[idx] = (k < D0r) ? w0[n*D0r + k] : 0.f;
}

// embed: writes fp32 x0 AND bf16 hi/lo directly into d_Ah/d_Al (fuses A-split)
__device__ __forceinline__ void emit_x(float* xrow, size_t base, int i, float v)
{
    xrow[i] = v;
    unsigned short hi = bh16(v);
    unsigned short lo = bh16(v - bh2f(hi));
    *((unsigned short*)d_Ah + base + i) = hi;
    *((unsigned short*)d_Al + base + i) = lo;
}

__global__ void embed_kernel(const int* __restrict__ word, const int* __restrict__ chars,
                             const int* __restrict__ pos,  const float* __restrict__ Ew,
                             const float* __restrict__ Ep, const float* __restrict__ cb)
{
    int bt  = blockIdx.x;
    int tid = threadIdx.x;
    __shared__ int cs[Lc];
    if (tid < Lc) cs[tid] = chars[bt*Lc + tid];
    int w = word[bt];
    int p = pos[bt];
    float* xrow = d_x0 + (size_t)bt*DP;
    size_t base = (size_t)bt*DP;
    for (int i = tid; i < WD; i += 128)  emit_x(xrow, base, i,       Ew[(size_t)w*WD + i]);
    for (int i = tid; i < PDm; i += 128) emit_x(xrow, base, 400 + i, Ep[p*PDm + i]);
    if (tid < DP - D0r) emit_x(xrow, base, D0r + tid, 0.f);
    __syncthreads();
    if (tid < NF) {
        int f = tid;
        float acc[Lc + 2];
        float bv = cb[f];
        #pragma unroll
        for (int q = 0; q < Lc + 2; q++) acc[q] = bv;
        #pragma unroll
        for (int j = 0; j < Lc; j++) {
            const float* u = d_U + cs[j]*300 + f;
            acc[j + 2] += u[0];
            acc[j + 1] += u[100];
            acc[j    ] += u[200];
        }
        float m = acc[0];
        #pragma unroll
        for (int q = 1; q < Lc + 2; q++) m = fmaxf(m, acc[q]);
        emit_x(xrow, base, WD + f, tanhf(m));
    }
}

// ---------------- counter init (once per replay) ----------------
__global__ void cntinit_kernel() { if (threadIdx.x < 64) g_cnt2[threadIdx.x] = 0; }

// ---------------- persistent BiLSTM recurrence (HMMA, 8 units/block) ----------
// grid = 64 blocks (2 dirs x 32 hidden-chunks of 8 units), 256 threads, co-resident.
// gates[64b x 32r] = h^T * w^T via mma.m16n8k16; 8 warps = 4 m-tiles x 2 n-tiles(16r).
// w bf16 hi/lo in smem (R8-validated k-chunk layout), h staged via cp.async (R13).
// smem: h_hi 32KB | h_lo 32KB | w_hi 16KB | w_lo 16KB | g_s [64][33] f32 8448B
#define SMEM_REC (65536 + 32768 + 8448)

__global__ void __launch_bounds__(256, 1)
recur_kernel(const float* __restrict__ gx, const float* __restrict__ whh,
             const float* __restrict__ mask, float* __restrict__ out,
             __nv_bfloat16* __restrict__ oah, __nv_bfloat16* __restrict__ oal,
             unsigned base)
{
    extern __shared__ __align__(1024) char smc[];
    uint32_t sb = s2u(smc);
    uint32_t wbv = sb + 65536;               // w hi; lo at +16384
    float* g_s = (float*)(smc + 98304);      // [64b][33]

    int tid = threadIdx.x, lane = tid & 31, wid = tid >> 5;
    int d   = blockIdx.x >> 5;
    int blk = blockIdx.x & 31;
    int j0  = blk * 8;

    int eb  = tid & 63;        // elementwise: batch
    int ejj = tid >> 6;        // elementwise: units ejj, ejj+4

    int mbase  = (wid >> 1)*16; // warp m-tile (batches)
    int nbase2 = (wid & 1)*16;  // warp n-tile (16 gate-rows)

    unsigned* cnt = &g_cnt2[d*32];

    // ---- fill w smem: rows r=0..31 (r = u*4+gate), k-chunks of 64 (R8 layout) ----
    for (int e = tid; e < 8192; e += 256) {
        int r = e >> 8, k = e & 255;
        int grow = d*G4 + (r & 3)*Hh + j0 + (r >> 2);
        float v = __ldg(whh + (size_t)grow*Hh + k);
        unsigned short hi = bh16(v);
        unsigned short lo = bh16(v - bh2f(hi));
        uint32_t off = (k >> 6)*4096 + r*128 + ((((k & 63)*2)) ^ ((r & 7) << 4));
        *(unsigned short*)(smc + 65536 + off)         = hi;
        *(unsigned short*)(smc + 65536 + 16384 + off) = lo;
    }

    // h0 = 0 (parity 1), 2 units per thread
    d_hh[1][d][(j0 + ejj)*64 + eb] = 0;
    d_hl[1][d][(j0 + ejj)*64 + eb] = 0;
    d_hh[1][d][(j0 + ejj + 4)*64 + eb] = 0;
    d_hl[1][d][(j0 + ejj + 4)*64 + eb] = 0;
    __syncthreads();
    if (tid == 0) red_add_rel(cnt);

    // fragment address components (R13/R8-validated)
    int krow_l = (lane & 7) + ((lane & 16) ? 8 : 0);
    int mseg_l = mbase*2 + ((lane & 8) ? 16 : 0);
    int nrow_l = (lane & 7) + ((lane & 16) ? 8 : 0);
    int bkel_l = (lane & 8) ? 8 : 0;
    int wr     = nbase2 + nrow_l;
    uint32_t wrow_off = wr*128;
    uint32_t wswz = (uint32_t)((wr & 7) << 4);

    float creg[2] = {0.f, 0.f}, hpreg[2] = {0.f, 0.f};

    for (int s = 0; s < Tn; s++) {
        int rp = (s & 1) ^ 1;
        int wp = s & 1;
        int t  = d ? (Tn - 1 - s) : s;

        // prefetch gx + mask for both cells (independent of barrier)
        float gxv[2][4];
        const float* gp = gx + ((size_t)(eb*Tn + t))*NW + d*G4 + j0 + ejj;
        gxv[0][0] = __ldg(gp);         gxv[0][1] = __ldg(gp + Hh);
        gxv[0][2] = __ldg(gp + 2*Hh);  gxv[0][3] = __ldg(gp + 3*Hh);
        gxv[1][0] = __ldg(gp + 4);     gxv[1][1] = __ldg(gp + Hh + 4);
        gxv[1][2] = __ldg(gp + 2*Hh + 4); gxv[1][3] = __ldg(gp + 3*Hh + 4);
        float mv  = __ldg(mask + eb*Tn + t);

        // wait for all 32 producers of h_{s-1}
        if (tid == 0) {
            unsigned tgt = base + 32u*(unsigned)(s + 1);
            while ((int)(ld_acq(cnt) - tgt) < 0) { }
        }
        __syncthreads();

        const unsigned short* HH = d_hh[rp][d];
        const unsigned short* HL = d_hl[rp][d];

        // cp.async stage h: group A = k 0..127, group B = k 128..255 (R13-validated)
        #pragma unroll
        for (int i = 0; i < 4; i++) {
            int g = i*256 + tid;
            int k = g >> 3, sg = g & 7;
            uint32_t off = k*128 + ((sg*16) ^ ((k & 7) << 4));
            cpa16(sb + off,         HH + g*8);
            cpa16(sb + 32768 + off, HL + g*8);
        }
        CP_COMMIT();
        #pragma unroll
        for (int i = 4; i < 8; i++) {
            int g = i*256 + tid;
            int k = g >> 3, sg = g & 7;
            uint32_t off = k*128 + ((sg*16) ^ ((k & 7) << 4));
            cpa16(sb + off,         HH + g*8);
            cpa16(sb + 32768 + off, HL + g*8);
        }
        CP_COMMIT();

        float acc0[4] = {0.f,0.f,0.f,0.f};
        float acc1[4] = {0.f,0.f,0.f,0.f};

        CP_WAIT1();
        __syncthreads();
        #pragma unroll
        for (int ks = 0; ks < 8; ks++) {
            int krow = ks*16 + krow_l;
            uint32_t ad = sb + krow*128 + ((uint32_t)mseg_l ^ ((krow & 7) << 4));
            uint32_t ahi[4], alo[4];
            ldsm4t(ahi, ad);
            ldsm4t(alo, ad + 32768);
            uint32_t bd = wbv + (ks >> 2)*4096 + wrow_off
                        + ((uint32_t)(((ks & 3)*16 + bkel_l)*2) ^ wswz);
            uint32_t th[4], tl[4];
            ldsm4(th, bd);
            ldsm4(tl, bd + 16384);
            uint32_t bh0[2] = {th[0], th[1]}, bh1[2] = {th[2], th[3]};
            uint32_t bl0[2] = {tl[0], tl[1]}, bl1[2] = {tl[2], tl[3]};
            mma16816(acc0, ahi, bh0); mma16816(acc0, ahi, bl0); mma16816(acc0, alo, bh0);
            mma16816(acc1, ahi, bh1); mma16816(acc1, ahi, bl1); mma16816(acc1, alo, bh1);
        }
        CP_WAIT0();
        __syncthreads();
        #pragma unroll
        for (int ks = 8; ks < 16; ks++) {
            int krow = ks*16 + krow_l;
            uint32_t ad = sb + krow*128 + ((uint32_t)mseg_l ^ ((krow & 7) << 4));
            uint32_t ahi[4], alo[4];
            ldsm4t(ahi, ad);
            ldsm4t(alo, ad + 32768);
            uint32_t bd = wbv + (ks >> 2)*4096 + wrow_off
                        + ((uint32_t)(((ks & 3)*16 + bkel_l)*2) ^ wswz);
            uint32_t th[4], tl[4];
            ldsm4(th, bd);
            ldsm4(tl, bd + 16384);
            uint32_t bh0[2] = {th[0], th[1]}, bh1[2] = {th[2], th[3]};
            uint32_t bl0[2] = {tl[0], tl[1]}, bl1[2] = {tl[2], tl[3]};
            mma16816(acc0, ahi, bh0); mma16816(acc0, ahi, bl0); mma16816(acc0, alo, bh0);
            mma16816(acc1, ahi, bh1); mma16816(acc1, ahi, bl1); mma16816(acc1, alo, bh1);
        }

        // store gate pre-activations g_s[b][r], stride 33 (conflict-free)
        {
            int bl = mbase + (lane >> 2);
            int cc = nbase2 + (lane & 3)*2;
            g_s[bl*33 + cc]           = acc0[0];
            g_s[bl*33 + cc + 1]       = acc0[1];
            g_s[(bl + 8)*33 + cc]     = acc0[2];
            g_s[(bl + 8)*33 + cc + 1] = acc0[3];
            g_s[bl*33 + cc + 8]           = acc1[0];
            g_s[bl*33 + cc + 9]           = acc1[1];
            g_s[(bl + 8)*33 + cc + 8]     = acc1[2];
            g_s[(bl + 8)*33 + cc + 9]     = acc1[3];
        }
        __syncthreads();

        // elementwise LSTM: 2 cells per thread (units ejj, ejj+4)
        float hnv[2];
        unsigned short hiv[2], lov[2];
        #pragma unroll
        for (int u2 = 0; u2 < 2; u2++) {
            int u = ejj + u2*4;
            const float* gr = g_s + eb*33 + u*4;
            float gi = gr[0] + gxv[u2][0];
            float gf = gr[1] + gxv[u2][1];
            float gg = gr[2] + gxv[u2][2];
            float go = gr[3] + gxv[u2][3];
            float ig = fsigmoid(gi);
            float fg = fsigmoid(gf);
            float og = fsigmoid(go);
            float gt = ftanh(gg);
            float cn = fg*creg[u2] + ig*gt;
            float hn = og*ftanh(cn);
            hn = mv*hn + (1.f - mv)*hpreg[u2];
            cn = mv*cn + (1.f - mv)*creg[u2];
            creg[u2] = cn;
            hpreg[u2] = hn;
            hnv[u2] = hn;
            unsigned short hi = bh16(hn);
            unsigned short lo = bh16(hn - bh2f(hi));
            hiv[u2] = hi; lov[u2] = lo;
            d_hh[wp][d][(j0 + u)*64 + eb] = hi;
            d_hl[wp][d][(j0 + u)*64 + eb] = lo;
        }
        __syncthreads();                       // all h stores done
        if (tid == 0) red_add_rel(cnt);        // release
        // off-critical-path: fp32 out + fused bf16 split for next layer's A
        size_t orow = (size_t)(eb*Tn + t);
        int col0 = d*Hh + j0 + ejj;
        out[orow*OUTW + col0]     = hnv[0];
        out[orow*OUTW + col0 + 4] = hnv[1];
        *((unsigned short*)oah + orow*DP + col0)     = hiv[0];
        *((unsigned short*)oal + orow*DP + col0)     = lov[0];
        *((unsigned short*)oah + orow*DP + col0 + 4) = hiv[1];
        *((unsigned short*)oal + orow*DP + col0 + 4) = lov[1];
    }
}

// ---------------- launch ----------------
extern "C" void kernel_launch(void* const* d_in, const int* in_sizes, int n_in,
                              void* d_out, int out_size)
{
    const int*   in_word  = (const int*)  d_in[0];
    const int*   in_char  = (const int*)  d_in[1];
    const int*   in_pos   = (const int*)  d_in[2];
    const float* mask     = (const float*)d_in[3];
    const float* emb_word = (const float*)d_in[4];
    const float* emb_char = (const float*)d_in[5];
    const float* emb_pos  = (const float*)d_in[6];
    const float* conv_w   = (const float*)d_in[7];
    const float* conv_b   = (const float*)d_in[8];
    const float* w_ih0    = (const float*)d_in[9];
    const float* w_hh0    = (const float*)d_in[10];
    const float* b0       = (const float*)d_in[11];
    const float* w_ih1    = (const float*)d_in[12];
    const float* w_hh1    = (const float*)d_in[13];
    const float* b1       = (const float*)d_in[14];
    const float* w_ih2    = (const float*)d_in[15];
    const float* w_hh2    = (const float*)d_in[16];
    const float* b2       = (const float*)d_in[17];
    float* out = (float*)d_out;

    cudaFuncSetAttribute(recur_kernel, cudaFuncAttributeMaxDynamicSharedMemorySize, SMEM_REC);
    cudaFuncSetAttribute(gemm_bf16_kernel, cudaFuncAttributeMaxDynamicSharedMemorySize, SMEM_GB);

    void *px1, *px2, *pgx, *pwpad, *pAh, *pAl;
    void *pWh0, *pWl0, *pWh1, *pWl1, *pWh2, *pWl2;
    cudaGetSymbolAddress(&px1,  d_x1);
    cudaGetSymbolAddress(&px2,  d_x2);
    cudaGetSymbolAddress(&pgx,  d_gx);
    cudaGetSymbolAddress(&pwpad, d_wpad);
    cudaGetSymbolAddress(&pAh, d_Ah);
    cudaGetSymbolAddress(&pAl, d_Al);
    cudaGetSymbolAddress(&pWh0, d_Wh0);
    cudaGetSymbolAddress(&pWl0, d_Wl0);
    cudaGetSymbolAddress(&pWh1, d_Wh1);
    cudaGetSymbolAddress(&pWl1, d_Wl1);
    cudaGetSymbolAddress(&pWh2, d_Wh2);
    cudaGetSymbolAddress(&pWl2, d_Wl2);

    cntinit_kernel<<<1, 64>>>();
    u_kernel<<<CVv, 128>>>(emb_char, conv_w);
    padw_kernel<<<(NW*DP + 255)/256, 256>>>(w_ih0);
    embed_kernel<<<BT, 128>>>(in_word, in_char, in_pos, emb_word, emb_pos, conv_b);

    const int nW4 = NW*DP/4;
    // all weight splits upfront
    split_kernel<<<(nW4 + 255)/256, 256>>>((const float*)pwpad,
        (__nv_bfloat16*)pWh0, (__nv_bfloat16*)pWl0, nW4);
    split_kernel<<<(nW4 + 255)/256, 256>>>(w_ih1,
        (__nv_bfloat16*)pWh1, (__nv_bfloat16*)pWl1, nW4);
    split_kernel<<<(nW4 + 255)/256, 256>>>(w_ih2,
        (__nv_bfloat16*)pWh2, (__nv_bfloat16*)pWl2, nW4);

    dim3 ggrid(NW/128, BT/128);
    const unsigned LAYER_ARR = 32u * 257u;   // arrivals per dir per layer

    // ---- layer 0 ----
    gemm_bf16_kernel<<<ggrid, 256, SMEM_GB>>>((const __nv_bfloat16*)pAh, (const __nv_bfloat16*)pAl,
        (const __nv_bfloat16*)pWh0, (const __nv_bfloat16*)pWl0, b0, (float*)pgx);
    recur_kernel<<<64, 256, SMEM_REC>>>((const float*)pgx, w_hh0, mask, (float*)px1,
        (__nv_bfloat16*)pAh, (__nv_bfloat16*)pAl, 0u);

    // ---- layer 1 ----
    gemm_bf16_kernel<<<ggrid, 256, SMEM_GB>>>((const __nv_bfloat16*)pAh, (const __nv_bfloat16*)pAl,
        (const __nv_bfloat16*)pWh1, (const __nv_bfloat16*)pWl1, b1, (float*)pgx);
    recur_kernel<<<64, 256, SMEM_REC>>>((const float*)pgx, w_hh1, mask, (float*)px2,
        (__nv_bfloat16*)pAh, (__nv_bfloat16*)pAl, LAYER_ARR);

    // ---- layer 2 ----
    gemm_bf16_kernel<<<ggrid, 256, SMEM_GB>>>((const __nv_bfloat16*)pAh, (const __nv_bfloat16*)pAl,
        (const __nv_bfloat16*)pWh2, (const __nv_bfloat16*)pWl2, b2, (float*)pgx);
    recur_kernel<<<64, 256, SMEM_REC>>>((const float*)pgx, w_hh2, mask, out,
        (__nv_bfloat16*)pAh, (__nv_bfloat16*)pAl, 2u*LAYER_ARR);
}

// round 16
// speedup vs baseline: 1.6803x; 1.6803x over previous
#include <cuda_runtime.h>
#include <cuda_bf16.h>
#include <cstdint>

typedef unsigned long long ull;

// ---------------- problem constants ----------------
#define Bsz   64
#define Tn    256
#define Lc    20
#define WD    300
#define CDm   100
#define PDm   100
#define NF    100
#define CVv   100
#define Hh    256
#define D0r   500
#define DP    512
#define G4    1024
#define NW    2048
#define BT    (Bsz*Tn)
#define OUTW  (2*Hh)

// ---------------- scratch (device globals; no runtime alloc) ----------------
__device__ __align__(256) float d_x0[BT*DP];
__device__ __align__(256) float d_x1[BT*OUTW];
__device__ __align__(256) float d_x2[BT*OUTW];
__device__ __align__(256) float d_gx[(size_t)BT*NW];
__device__ __align__(256) float d_wpad[NW*DP];
__device__ float d_U[CVv*3*NF];
__device__ __align__(256) unsigned short d_hh[2][2][Hh*Bsz];  // h hi bf16, [parity][dir][j*64+b]
__device__ __align__(256) unsigned short d_hl[2][2][Hh*Bsz];  // h lo bf16
__device__ __align__(256) __nv_bfloat16 d_Ah[BT*DP];
__device__ __align__(256) __nv_bfloat16 d_Al[BT*DP];
__device__ __align__(256) __nv_bfloat16 d_Wh0[NW*DP];
__device__ __align__(256) __nv_bfloat16 d_Wl0[NW*DP];
__device__ __align__(256) __nv_bfloat16 d_Wh1[NW*DP];
__device__ __align__(256) __nv_bfloat16 d_Wl1[NW*DP];
__device__ __align__(256) __nv_bfloat16 d_Wh2[NW*DP];
__device__ __align__(256) __nv_bfloat16 d_Wl2[NW*DP];
__device__ __align__(256) unsigned g_cnt2[64];   // [0]=dir0, [32]=dir1 (separate lines)

// ---------------- ptx helpers (compute_103-safe only) ----------------
__device__ __forceinline__ uint32_t s2u(const void* p){
    uint32_t a;
    asm("{ .reg .u64 t; cvta.to.shared.u64 t, %1; cvt.u32.u64 %0, t; }" : "=r"(a) : "l"(p));
    return a;
}
__device__ __forceinline__ void ldsm4(uint32_t* r, uint32_t addr){
    asm volatile("ldmatrix.sync.aligned.m8n8.x4.shared.b16 {%0,%1,%2,%3}, [%4];"
        : "=r"(r[0]), "=r"(r[1]), "=r"(r[2]), "=r"(r[3]) : "r"(addr));
}
__device__ __forceinline__ void ldsm4t(uint32_t* r, uint32_t addr){
    asm volatile("ldmatrix.sync.aligned.m8n8.x4.trans.shared.b16 {%0,%1,%2,%3}, [%4];"
        : "=r"(r[0]), "=r"(r[1]), "=r"(r[2]), "=r"(r[3]) : "r"(addr));
}
__device__ __forceinline__ void mma16816(float* c, const uint32_t* a, const uint32_t* b){
    asm volatile("mma.sync.aligned.m16n8k16.row.col.f32.bf16.bf16.f32 "
        "{%0,%1,%2,%3}, {%4,%5,%6,%7}, {%8,%9}, {%0,%1,%2,%3};"
        : "+f"(c[0]), "+f"(c[1]), "+f"(c[2]), "+f"(c[3])
        : "r"(a[0]), "r"(a[1]), "r"(a[2]), "r"(a[3]), "r"(b[0]), "r"(b[1]));
}
__device__ __forceinline__ void cpa16(uint32_t dst, const void* src){
    asm volatile("cp.async.cg.shared.global [%0], [%1], 16;" :: "r"(dst), "l"(src) : "memory");
}
#define CP_COMMIT() asm volatile("cp.async.commit_group;" ::: "memory")
#define CP_WAIT0()  asm volatile("cp.async.wait_group 0;" ::: "memory")
#define CP_WAIT1()  asm volatile("cp.async.wait_group 1;" ::: "memory")

__device__ __forceinline__ unsigned ld_acq(const unsigned* p){
    unsigned v;
    asm volatile("ld.acquire.gpu.global.b32 %0, [%1];" : "=r"(v) : "l"(p) : "memory");
    return v;
}
__device__ __forceinline__ void red_add_rel(unsigned* p){
    asm volatile("red.release.gpu.global.add.u32 [%0], 1;" :: "l"(p) : "memory");
}

// fast NaN-safe activations (err ~2^-21, budget 1e-3)
__device__ __forceinline__ float fsigmoid(float x){
    return __fdividef(1.f, 1.f + __expf(-x));
}
__device__ __forceinline__ float ftanh(float x){
    return 1.f - __fdividef(2.f, __expf(2.f*x) + 1.f);
}

__device__ __forceinline__ unsigned short bh16(float x){
    __nv_bfloat16 h = __float2bfloat16(x);
    return *(unsigned short*)&h;
}
__device__ __forceinline__ float bh2f(unsigned short u){
    __nv_bfloat16 h = *(__nv_bfloat16*)&u;
    return __bfloat162float(h);
}
__device__ __forceinline__ unsigned pk_hi(float x, float y){
    return (unsigned)bh16(x) | ((unsigned)bh16(y) << 16);
}
__device__ __forceinline__ unsigned pk_lo(float x, float y){
    float rx = x - bh2f(bh16(x));
    float ry = y - bh2f(bh16(y));
    return (unsigned)bh16(rx) | ((unsigned)bh16(ry) << 16);
}

// ---------------- fp32 -> bf16 hi/lo split ----------------
__global__ void split_kernel(const float* __restrict__ x,
                             __nv_bfloat16* __restrict__ hi,
                             __nv_bfloat16* __restrict__ lo, int n4)
{
    int i = blockIdx.x*256 + threadIdx.x;
    if (i >= n4) return;
    float4 v = ((const float4*)x)[i];
    float a[4] = {v.x, v.y, v.z, v.w};
    unsigned short hs[4], ls[4];
    #pragma unroll
    for (int j = 0; j < 4; j++) {
        hs[j] = bh16(a[j]);
        ls[j] = bh16(a[j] - bh2f(hs[j]));
    }
    ull hv = (ull)hs[0] | ((ull)hs[1]<<16) | ((ull)hs[2]<<32) | ((ull)hs[3]<<48);
    ull lv = (ull)ls[0] | ((ull)ls[1]<<16) | ((ull)ls[2]<<32) | ((ull)ls[3]<<48);
    *(ull*)(hi + 4*(size_t)i) = hv;
    *(ull*)(lo + 4*(size_t)i) = lv;
}

// ---------------- split-bf16 tensor-core GEMM (unchanged from R8) ----------------
#define SMEM_GB 131072

__global__ void __launch_bounds__(256) gemm_bf16_kernel(
    const __nv_bfloat16* __restrict__ Ah, const __nv_bfloat16* __restrict__ Al,
    const __nv_bfloat16* __restrict__ Wh, const __nv_bfloat16* __restrict__ Wl,
    const float* __restrict__ bias, float* __restrict__ C)
{
    extern __shared__ __align__(1024) char smem[];
    uint32_t sb = s2u(smem);
    int tid = threadIdx.x, lane = tid & 31, wid = tid >> 5;
    int bm = blockIdx.y*128, bn = blockIdx.x*128;
    int wm = (wid >> 1)*32, wn = (wid & 1)*64;

    const __nv_bfloat16* srcs[4];
    srcs[0] = Ah + (size_t)bm*DP;
    srcs[1] = Al + (size_t)bm*DP;
    srcs[2] = Wh + (size_t)bn*DP;
    srcs[3] = Wl + (size_t)bn*DP;

    int r  = tid >> 1;
    int s0 = (tid & 1)*4;
    uint32_t dbase = r*128;

    float acc[2][8][4];
    #pragma unroll
    for (int i = 0; i < 2; i++)
        #pragma unroll
        for (int j = 0; j < 8; j++)
            #pragma unroll
            for (int q = 0; q < 4; q++) acc[i][j][q] = 0.f;

    #pragma unroll
    for (int m = 0; m < 4; m++) {
        const __nv_bfloat16* src = srcs[m] + (size_t)r*DP + s0*8;
        uint32_t d = sb + m*16384 + dbase;
        #pragma unroll
        for (int i = 0; i < 4; i++)
            cpa16(d + (((s0+i)*16) ^ ((r&7)<<4)), src + i*8);
    }
    CP_COMMIT();

    int arow_l = (lane&7) + ((lane&8) ? 8 : 0);
    int akel_l = (lane&16) ? 8 : 0;
    int nrow_l = (lane&7) + ((lane&16) ? 8 : 0);
    int bkel_l = (lane&8) ? 8 : 0;

    for (int ch = 0; ch < 8; ch++) {
        CP_WAIT0();
        __syncthreads();
        if (ch < 7) {
            uint32_t base = sb + ((ch+1)&1)*65536;
            #pragma unroll
            for (int m = 0; m < 4; m++) {
                const __nv_bfloat16* src = srcs[m] + (size_t)r*DP + (ch+1)*64 + s0*8;
                uint32_t d = base + m*16384 + dbase;
                #pragma unroll
                for (int i = 0; i < 4; i++)
                    cpa16(d + (((s0+i)*16) ^ ((r&7)<<4)), src + i*8);
            }
            CP_COMMIT();
        }
        uint32_t bb = sb + (ch&1)*65536;
        #pragma unroll
        for (int s = 0; s < 4; s++) {
            uint32_t a_h[2][4], a_l[2][4];
            #pragma unroll
            for (int mt = 0; mt < 2; mt++) {
                int row = wm + mt*16 + arow_l;
                int kel = s*16 + akel_l;
                uint32_t ad = bb + row*128 + ((kel*2) ^ ((row&7)<<4));
                ldsm4(a_h[mt], ad);
                ldsm4(a_l[mt], ad + 16384);
            }
            uint32_t b_h[8][2], b_l[8][2];
            #pragma unroll
            for (int g = 0; g < 4; g++) {
                int row = wn + g*16 + nrow_l;
                int kel = s*16 + bkel_l;
                uint32_t ad = bb + 32768 + row*128 + ((kel*2) ^ ((row&7)<<4));
                uint32_t t4[4];
                ldsm4(t4, ad);
                b_h[2*g][0] = t4[0]; b_h[2*g][1] = t4[1];
                b_h[2*g+1][0] = t4[2]; b_h[2*g+1][1] = t4[3];
                ldsm4(t4, ad + 16384);
                b_l[2*g][0] = t4[0]; b_l[2*g][1] = t4[1];
                b_l[2*g+1][0] = t4[2]; b_l[2*g+1][1] = t4[3];
            }
            #pragma unroll
            for (int i = 0; i < 2; i++)
                #pragma unroll
                for (int j = 0; j < 8; j++) {
                    mma16816(acc[i][j], a_h[i], b_h[j]);
                    mma16816(acc[i][j], a_h[i], b_l[j]);
                    mma16816(acc[i][j], a_l[i], b_h[j]);
                }
        }
    }

    int rr = lane >> 2, cc = (lane & 3)*2;
    #pragma unroll
    for (int i = 0; i < 2; i++) {
        #pragma unroll
        for (int j = 0; j < 8; j++) {
            int row = bm + wm + i*16 + rr;
            int col = bn + wn + j*8 + cc;
            float bx = __ldg(bias + col), by = __ldg(bias + col + 1);
            float2 v0 = make_float2(acc[i][j][0] + bx, acc[i][j][1] + by);
            float2 v1 = make_float2(acc[i][j][2] + bx, acc[i][j][3] + by);
            *(float2*)(C + (size_t)row*NW + col) = v0;
            *(float2*)(C + (size_t)(row+8)*NW + col) = v1;
        }
    }
}

// ---------------- U[v][k][f] ----------------
__global__ void u_kernel(const float* __restrict__ Ec, const float* __restrict__ cw)
{
    int v = blockIdx.x;
    int f = threadIdx.x;
    __shared__ float e[CDm];
    if (f < CDm) e[f] = Ec[v*CDm + f];
    __syncthreads();
    if (f < NF) {
        float a0 = 0.f, a1 = 0.f, a2 = 0.f;
        #pragma unroll 4
        for (int c = 0; c < CDm; c++) {
            float ev = e[c];
            const float* wp = cw + f*(CDm*3) + c*3;
            a0 += ev*wp[0]; a1 += ev*wp[1]; a2 += ev*wp[2];
        }
        d_U[v*300 +       f] = a0;
        d_U[v*300 + 100 + f] = a1;
        d_U[v*300 + 200 + f] = a2;
    }
}

__global__ void padw_kernel(const float* __restrict__ w0)
{
    int idx = blockIdx.x*256 + threadIdx.x;
    if (idx >= NW*DP) return;
    int n = idx >> 9, k = idx & 511;
    d_wpad[idx] = (k < D0r) ? w0[n*D0r + k] : 0.f;
}

__global__ void embed_kernel(const int* __restrict__ word, const int* __restrict__ chars,
                             const int* __restrict__ pos,  const float* __restrict__ Ew,
                             const float* __restrict__ Ep, const float* __restrict__ cb)
{
    int bt  = blockIdx.x;
    int tid = threadIdx.x;
    __shared__ int cs[Lc];
    if (tid < Lc) cs[tid] = chars[bt*Lc + tid];
    int w = word[bt];
    int p = pos[bt];
    float* xrow = d_x0 + (size_t)bt*DP;
    for (int i = tid; i < WD; i += 128)  xrow[i]       = Ew[(size_t)w*WD + i];
    for (int i = tid; i < PDm; i += 128) xrow[400 + i] = Ep[p*PDm + i];
    if (tid < DP - D0r) xrow[D0r + tid] = 0.f;
    __syncthreads();
    if (tid < NF) {
        int f = tid;
        float acc[Lc + 2];
        float bv = cb[f];
        #pragma unroll
        for (int q = 0; q < Lc + 2; q++) acc[q] = bv;
        #pragma unroll
        for (int j = 0; j < Lc; j++) {
            const float* u = d_U + cs[j]*300 + f;
            acc[j + 2] += u[0];
            acc[j + 1] += u[100];
            acc[j    ] += u[200];
        }
        float m = acc[0];
        #pragma unroll
        for (int q = 1; q < Lc + 2; q++) m = fmaxf(m, acc[q]);
        xrow[WD + f] = tanhf(m);
    }
}

// ---------------- counter init (once per replay) ----------------
__global__ void cntinit_kernel() { if (threadIdx.x < 64) g_cnt2[threadIdx.x] = 0; }

// ---------------- persistent BiLSTM recurrence (R13 + step-ahead gx prefetch) ----
// grid = 128 blocks (2 dirs x 64 hidden-chunks of 4 units), 256 threads, co-resident.
// gates[64b x 16r] = h^T * w^T via mma.m16n8k16; w fragments register-resident;
// h (bf16 hi/lo) staged global->smem via cp.async in 2 groups, MMA overlaps.
// gx/mask for step s are LDG-issued right after step s-1's release (full-step lead).
#define SMEM_REC (65536 + 4096)

__global__ void __launch_bounds__(256, 1)
recur_kernel(const float* __restrict__ gx, const float* __restrict__ whh,
             const float* __restrict__ mask, float* __restrict__ out, unsigned base)
{
    extern __shared__ __align__(1024) char smc[];
    uint32_t sb = s2u(smc);
    float* g_s = (float*)(smc + 65536);

    int tid = threadIdx.x, lane = tid & 31, wid = tid >> 5;
    int d   = blockIdx.x >> 6;
    int blk = blockIdx.x & 63;
    int j0  = blk * 4;

    int eb  = tid & 63;
    int ejj = tid >> 6;

    int mbase = (wid >> 1)*16;
    int nbase = (wid & 1)*8;

    unsigned* cnt = &g_cnt2[d*32];

    // ---- preload w fragments (register-resident, R11-validated mapping) ----
    unsigned bwh[16][2], bwl[16][2];
    {
        int r = nbase + (lane >> 2);
        int grow = d*G4 + (r & 3)*Hh + j0 + (r >> 2);
        const float* wrow = whh + (size_t)grow*Hh;
        #pragma unroll
        for (int ks = 0; ks < 16; ks++) {
            int c = ks*16 + (lane & 3)*2;
            float a0 = __ldg(wrow + c),     a1 = __ldg(wrow + c + 1);
            float a2 = __ldg(wrow + c + 8), a3 = __ldg(wrow + c + 9);
            bwh[ks][0] = pk_hi(a0, a1);  bwl[ks][0] = pk_lo(a0, a1);
            bwh[ks][1] = pk_hi(a2, a3);  bwl[ks][1] = pk_lo(a2, a3);
        }
    }

    // h0 = 0 (parity 1)
    d_hh[1][d][(j0 + ejj)*64 + eb] = 0;
    d_hl[1][d][(j0 + ejj)*64 + eb] = 0;
    __syncthreads();
    if (tid == 0) red_add_rel(cnt);

    int krow_l = (lane & 7) + ((lane & 16) ? 8 : 0);
    int mseg_l = mbase*2 + ((lane & 8) ? 16 : 0);

    float creg = 0.f, hpreg = 0.f;

    // prefetch gx/mask for step 0 (consumed late in step 0)
    float gxi, gxf, gxg, gxo, mv;
    {
        int t0 = d ? (Tn - 1) : 0;
        const float* gp = gx + ((size_t)(eb*Tn + t0))*NW + d*G4 + j0 + ejj;
        gxi = __ldg(gp);
        gxf = __ldg(gp + Hh);
        gxg = __ldg(gp + 2*Hh);
        gxo = __ldg(gp + 3*Hh);
        mv  = __ldg(mask + eb*Tn + t0);
    }

    for (int s = 0; s < Tn; s++) {
        int rp = (s & 1) ^ 1;
        int wp = s & 1;
        int t  = d ? (Tn - 1 - s) : s;

        // wait for all 64 producers of h_{s-1}
        if (tid == 0) {
            unsigned tgt = base + 64u*(unsigned)(s + 1);
            while ((int)(ld_acq(cnt) - tgt) < 0) { }
        }
        __syncthreads();

        const unsigned short* HH = d_hh[rp][d];
        const unsigned short* HL = d_hl[rp][d];

        // ---- cp.async stage: group A = k 0..127, group B = k 128..255 ----
        #pragma unroll
        for (int i = 0; i < 4; i++) {
            int g = i*256 + tid;
            int k = g >> 3, sg = g & 7;
            uint32_t off = k*128 + ((sg*16) ^ ((k & 7) << 4));
            cpa16(sb + off,         HH + g*8);
            cpa16(sb + 32768 + off, HL + g*8);
        }
        CP_COMMIT();
        #pragma unroll
        for (int i = 4; i < 8; i++) {
            int g = i*256 + tid;
            int k = g >> 3, sg = g & 7;
            uint32_t off = k*128 + ((sg*16) ^ ((k & 7) << 4));
            cpa16(sb + off,         HH + g*8);
            cpa16(sb + 32768 + off, HL + g*8);
        }
        CP_COMMIT();

        float acc[4] = {0.f, 0.f, 0.f, 0.f};

        CP_WAIT1();
        __syncthreads();
        #pragma unroll
        for (int ks = 0; ks < 8; ks++) {
            int krow = ks*16 + krow_l;
            uint32_t ad = sb + krow*128 + ((uint32_t)mseg_l ^ ((krow & 7) << 4));
            uint32_t ahi[4], alo[4];
            ldsm4t(ahi, ad);
            ldsm4t(alo, ad + 32768);
            mma16816(acc, ahi, bwh[ks]);
            mma16816(acc, ahi, bwl[ks]);
            mma16816(acc, alo, bwh[ks]);
        }
        CP_WAIT0();
        __syncthreads();
        #pragma unroll
        for (int ks = 8; ks < 16; ks++) {
            int krow = ks*16 + krow_l;
            uint32_t ad = sb + krow*128 + ((uint32_t)mseg_l ^ ((krow & 7) << 4));
            uint32_t ahi[4], alo[4];
            ldsm4t(ahi, ad);
            ldsm4t(alo, ad + 32768);
            mma16816(acc, ahi, bwh[ks]);
            mma16816(acc, ahi, bwl[ks]);
            mma16816(acc, alo, bwh[ks]);
        }

        // ---- write gate pre-activations to smem g_s[b][r] ----
        {
            int bl = mbase + (lane >> 2);
            int rr = nbase + (lane & 3)*2;
            *(float2*)&g_s[bl*16 + rr]       = make_float2(acc[0], acc[1]);
            *(float2*)&g_s[(bl + 8)*16 + rr] = make_float2(acc[2], acc[3]);
        }
        __syncthreads();

        // ---- elementwise LSTM: one (batch, unit) cell per thread ----
        float hn;
        {
            const float* gr = g_s + eb*16 + ejj*4;
            float gi = gr[0] + gxi;
            float gf = gr[1] + gxf;
            float gg = gr[2] + gxg;
            float go = gr[3] + gxo;
            float ig = fsigmoid(gi);
            float fg = fsigmoid(gf);
            float og = fsigmoid(go);
            float gt = ftanh(gg);
            float cn = fg*creg + ig*gt;
            hn = og*ftanh(cn);
            hn = mv*hn + (1.f - mv)*hpreg;
            cn = mv*cn + (1.f - mv)*creg;
            creg = cn;
            hpreg = hn;
            unsigned short hi = bh16(hn);
            unsigned short lo = bh16(hn - bh2f(hi));
            d_hh[wp][d][(j0 + ejj)*64 + eb] = hi;
            d_hl[wp][d][(j0 + ejj)*64 + eb] = lo;
        }
        __syncthreads();                       // all h stores done
        if (tid == 0) red_add_rel(cnt);        // release

        // off the critical path: out store for step s, then prefetch gx for s+1
        out[((size_t)(eb*Tn + t))*OUTW + d*Hh + j0 + ejj] = hn;
        if (s + 1 < Tn) {
            int tn = d ? (Tn - 2 - s) : (s + 1);
            const float* gp = gx + ((size_t)(eb*Tn + tn))*NW + d*G4 + j0 + ejj;
            gxi = __ldg(gp);
            gxf = __ldg(gp + Hh);
            gxg = __ldg(gp + 2*Hh);
            gxo = __ldg(gp + 3*Hh);
            mv  = __ldg(mask + eb*Tn + tn);
        }
    }
}

// ---------------- launch ----------------
extern "C" void kernel_launch(void* const* d_in, const int* in_sizes, int n_in,
                              void* d_out, int out_size)
{
    const int*   in_word  = (const int*)  d_in[0];
    const int*   in_char  = (const int*)  d_in[1];
    const int*   in_pos   = (const int*)  d_in[2];
    const float* mask     = (const float*)d_in[3];
    const float* emb_word = (const float*)d_in[4];
    const float* emb_char = (const float*)d_in[5];
    const float* emb_pos  = (const float*)d_in[6];
    const float* conv_w   = (const float*)d_in[7];
    const float* conv_b   = (const float*)d_in[8];
    const float* w_ih0    = (const float*)d_in[9];
    const float* w_hh0    = (const float*)d_in[10];
    const float* b0       = (const float*)d_in[11];
    const float* w_ih1    = (const float*)d_in[12];
    const float* w_hh1    = (const float*)d_in[13];
    const float* b1       = (const float*)d_in[14];
    const float* w_ih2    = (const float*)d_in[15];
    const float* w_hh2    = (const float*)d_in[16];
    const float* b2       = (const float*)d_in[17];
    float* out = (float*)d_out;

    cudaFuncSetAttribute(recur_kernel, cudaFuncAttributeMaxDynamicSharedMemorySize, SMEM_REC);
    cudaFuncSetAttribute(gemm_bf16_kernel, cudaFuncAttributeMaxDynamicSharedMemorySize, SMEM_GB);

    void *px0, *px1, *px2, *pgx, *pwpad, *pAh, *pAl;
    void *pWh0, *pWl0, *pWh1, *pWl1, *pWh2, *pWl2;
    cudaGetSymbolAddress(&px0,  d_x0);
    cudaGetSymbolAddress(&px1,  d_x1);
    cudaGetSymbolAddress(&px2,  d_x2);
    cudaGetSymbolAddress(&pgx,  d_gx);
    cudaGetSymbolAddress(&pwpad, d_wpad);
    cudaGetSymbolAddress(&pAh, d_Ah);
    cudaGetSymbolAddress(&pAl, d_Al);
    cudaGetSymbolAddress(&pWh0, d_Wh0);
    cudaGetSymbolAddress(&pWl0, d_Wl0);
    cudaGetSymbolAddress(&pWh1, d_Wh1);
    cudaGetSymbolAddress(&pWl1, d_Wl1);
    cudaGetSymbolAddress(&pWh2, d_Wh2);
    cudaGetSymbolAddress(&pWl2, d_Wl2);

    cntinit_kernel<<<1, 64>>>();
    u_kernel<<<CVv, 128>>>(emb_char, conv_w);
    padw_kernel<<<(NW*DP + 255)/256, 256>>>(w_ih0);
    embed_kernel<<<BT, 128>>>(in_word, in_char, in_pos, emb_word, emb_pos, conv_b);

    const int nA4 = BT*DP/4;
    const int nW4 = NW*DP/4;
    const unsigned LAYER_ARR = 64u * 257u;

    // all weight splits upfront (off the per-layer critical path)
    split_kernel<<<(nW4 + 255)/256, 256>>>((const float*)pwpad,
        (__nv_bfloat16*)pWh0, (__nv_bfloat16*)pWl0, nW4);
    split_kernel<<<(nW4 + 255)/256, 256>>>(w_ih1,
        (__nv_bfloat16*)pWh1, (__nv_bfloat16*)pWl1, nW4);
    split_kernel<<<(nW4 + 255)/256, 256>>>(w_ih2,
        (__nv_bfloat16*)pWh2, (__nv_bfloat16*)pWl2, nW4);

    dim3 ggrid(NW/128, BT/128);

    // ---- layer 0 ----
    split_kernel<<<(nA4 + 255)/256, 256>>>((const float*)px0,
        (__nv_bfloat16*)pAh, (__nv_bfloat16*)pAl, nA4);
    gemm_bf16_kernel<<<ggrid, 256, SMEM_GB>>>((const __nv_bfloat16*)pAh, (const __nv_bfloat16*)pAl,
        (const __nv_bfloat16*)pWh0, (const __nv_bfloat16*)pWl0, b0, (float*)pgx);
    recur_kernel<<<128, 256, SMEM_REC>>>((const float*)pgx, w_hh0, mask, (float*)px1, 0u);

    // ---- layer 1 ----
    split_kernel<<<(nA4 + 255)/256, 256>>>((const float*)px1,
        (__nv_bfloat16*)pAh, (__nv_bfloat16*)pAl, nA4);
    gemm_bf16_kernel<<<ggrid, 256, SMEM_GB>>>((const __nv_bfloat16*)pAh, (const __nv_bfloat16*)pAl,
        (const __nv_bfloat16*)pWh1, (const __nv_bfloat16*)pWl1, b1, (float*)pgx);
    recur_kernel<<<128, 256, SMEM_REC>>>((const float*)pgx, w_hh1, mask, (float*)px2, LAYER_ARR);

    // ---- layer 2 ----
    split_kernel<<<(nA4 + 255)/256, 256>>>((const float*)px2,
        (__nv_bfloat16*)pAh, (__nv_bfloat16*)pAl, nA4);
    gemm_bf16_kernel<<<ggrid, 256, SMEM_GB>>>((const __nv_bfloat16*)pAh, (const __nv_bfloat16*)pAl,
        (const __nv_bfloat16*)pWh2, (const __nv_bfloat16*)pWl2, b2, (float*)pgx);
    recur_kernel<<<128, 256, SMEM_REC>>>((const float*)pgx, w_hh2, mask, out, 2u*LAYER_ARR);
}